// round 4
// baseline (speedup 1.0000x reference)
#include <cuda_runtime.h>

// DepthwiseStencil3D: x (1,16,128,128,128) fp32 -> out flat channels ch = c*6+k.
// Taps (k): 0 -> w+1, 1 -> w-1, 2 -> h+1, 3 -> h-1, 4 -> d+1, 5 -> d-1.
//
// h-pair register tiling: each thread produces rows h and h+1 (h even) of one
// (c, d, w4) column. Rows h-1..h+2 are loaded once and reused as both centers
// and h±1 taps. 8 front-batched float4 loads + 12 streaming float4 stores
// per thread. Warp spans exactly one W row, so w±1 comes from shuffles.

#define C_ 16
#define D_ 128
#define H_ 128
#define W_ 128
#define HW_ (H_ * W_)          // 16384
#define DHW_ (D_ * HW_)        // 2097152

__global__ void __launch_bounds__(256) stencil6_kernel(
    const float* __restrict__ x, float* __restrict__ out)
{
    // tid enumerates (c, d, h2, w4): 16 * 128 * 64 * 32 = 4,194,304 threads
    int tid = blockIdx.x * blockDim.x + threadIdx.x;

    int w4 = tid & 31;            // float4 index along W == lane id
    int h  = ((tid >> 5) & 63) << 1;   // even h: 0, 2, ..., 126
    int d  = (tid >> 11) & 127;
    int c  = tid >> 18;           // 0..15

    int spatial = d * HW_ + h * W_ + (w4 << 2);  // row h, within-channel offset
    int base    = c * DHW_ + spatial;            // element index into x (row h)
    int b4      = base >> 2;                     // float4 index (row h)

    const float4* __restrict__ x4 = reinterpret_cast<const float4*>(x);
    float4* __restrict__ o4 = reinterpret_cast<float4*>(out);

    const float4 zero4 = make_float4(0.f, 0.f, 0.f, 0.f);
    const int W4 = W_ >> 2;        // 32 float4 per row
    const int HW4 = HW_ >> 2;      // float4 per d-slab

    // Front-batched loads: 4 h-rows + 4 d-neighbors (zero pad at volume edges).
    float4 vm1 = (h > 0)       ? x4[b4 - W4]  : zero4;   // row h-1
    float4 v0  =                 x4[b4];                 // row h   (center A)
    float4 v1  =                 x4[b4 + W4];            // row h+1 (center B)
    float4 v2  = (h < H_ - 2)  ? x4[b4 + 2*W4] : zero4;  // row h+2
    float4 vdp0 = (d < D_ - 1) ? x4[b4 + HW4]       : zero4;  // d+1, row h
    float4 vdm0 = (d > 0)      ? x4[b4 - HW4]       : zero4;  // d-1, row h
    float4 vdp1 = (d < D_ - 1) ? x4[b4 + HW4 + W4]  : zero4;  // d+1, row h+1
    float4 vdm1 = (d > 0)      ? x4[b4 - HW4 + W4]  : zero4;  // d-1, row h+1

    // w-edge scalars via intra-warp shuffle (warp == one W row).
    unsigned full = 0xffffffffu;
    float xl0 = __shfl_up_sync(full, v0.w, 1);
    float xr0 = __shfl_down_sync(full, v0.x, 1);
    float xl1 = __shfl_up_sync(full, v1.w, 1);
    float xr1 = __shfl_down_sync(full, v1.x, 1);
    if (w4 == 0)  { xl0 = 0.f; xl1 = 0.f; }   // w = -1 padding
    if (w4 == 31) { xr0 = 0.f; xr1 = 0.f; }   // w = 128 padding

    // w-shift taps for both rows.
    float4 k0a = make_float4(v0.y, v0.z, v0.w, xr0);   // row h,   w+1
    float4 k1a = make_float4(xl0, v0.x, v0.y, v0.z);   // row h,   w-1
    float4 k0b = make_float4(v1.y, v1.z, v1.w, xr1);   // row h+1, w+1
    float4 k1b = make_float4(xl1, v1.x, v1.y, v1.z);   // row h+1, w-1

    // Output: flat channel ch = c*6 + k. Offset = (c*6 + k)*DHW + spatial.
    int ob4 = ((c * 6) * DHW_ + spatial) >> 2;   // k = 0 slot, row h
    const int ks4 = DHW_ >> 2;                   // float4 stride between taps

    // Row h (taps: w+1, w-1, h+1=v1, h-1=vm1, d+1, d-1)
    __stcs(&o4[ob4],           k0a);
    __stcs(&o4[ob4 + 1 * ks4], k1a);
    __stcs(&o4[ob4 + 2 * ks4], v1);
    __stcs(&o4[ob4 + 3 * ks4], vm1);
    __stcs(&o4[ob4 + 4 * ks4], vdp0);
    __stcs(&o4[ob4 + 5 * ks4], vdm0);

    // Row h+1 (taps: w+1, w-1, h+1=v2, h-1=v0, d+1, d-1)
    int ob4b = ob4 + W4;
    __stcs(&o4[ob4b],           k0b);
    __stcs(&o4[ob4b + 1 * ks4], k1b);
    __stcs(&o4[ob4b + 2 * ks4], v2);
    __stcs(&o4[ob4b + 3 * ks4], v0);
    __stcs(&o4[ob4b + 4 * ks4], vdp1);
    __stcs(&o4[ob4b + 5 * ks4], vdm1);
}

extern "C" void kernel_launch(void* const* d_in, const int* in_sizes, int n_in,
                              void* d_out, int out_size)
{
    const float* x = (const float*)d_in[0];
    float* out = (float*)d_out;

    const int threads = 256;
    const int total = (C_ * DHW_) / 8;     // 4,194,304 threads (2 rows each)
    const int blocks = total / threads;    // 16384

    stencil6_kernel<<<blocks, threads>>>(x, out);
}

// round 5
// speedup vs baseline: 1.0156x; 1.0156x over previous
#include <cuda_runtime.h>
#include <cstdint>

// DepthwiseStencil3D: x (1,16,128,128,128) fp32 -> out flat channels ch = c*6+k.
// Taps (k): 0 -> w+1, 1 -> w-1, 2 -> h+1, 3 -> h-1, 4 -> d+1, 5 -> d-1.
//
// 256-bit variant: one thread per 8 floats along W (sm_100+ v8.b32 ld/st).
// 5 x 32B loads + 6 x 32B streaming stores per thread. Lanes 0-15 of a warp
// cover one W row, lanes 16-31 the next; w-edge scalars come from shuffles
// (cross-row shuffle results are masked to zero by the w-padding predicate).

#define C_ 16
#define D_ 128
#define H_ 128
#define W_ 128
#define HW_ (H_ * W_)          // 16384
#define DHW_ (D_ * HW_)        // 2097152

struct V8 { uint32_t r[8]; };

__device__ __forceinline__ V8 ldg_v8(const float* p) {
    V8 v;
    asm volatile("ld.global.v8.b32 {%0,%1,%2,%3,%4,%5,%6,%7}, [%8];"
                 : "=r"(v.r[0]), "=r"(v.r[1]), "=r"(v.r[2]), "=r"(v.r[3]),
                   "=r"(v.r[4]), "=r"(v.r[5]), "=r"(v.r[6]), "=r"(v.r[7])
                 : "l"(p));
    return v;
}

__device__ __forceinline__ void stg_cs_v8(float* p, const V8& v) {
    asm volatile("st.global.cs.v8.b32 [%0], {%1,%2,%3,%4,%5,%6,%7,%8};"
                 :: "l"(p),
                    "r"(v.r[0]), "r"(v.r[1]), "r"(v.r[2]), "r"(v.r[3]),
                    "r"(v.r[4]), "r"(v.r[5]), "r"(v.r[6]), "r"(v.r[7])
                 : "memory");
}

__global__ void __launch_bounds__(256) stencil6_kernel(
    const float* __restrict__ x, float* __restrict__ out)
{
    // tid enumerates (c, d, h, w8): 16 * 128 * 128 * 16 = 4,194,304 threads
    int tid = blockIdx.x * blockDim.x + threadIdx.x;

    int w8 = tid & 15;            // 8-float chunk index along W (W/8 = 16)
    int h  = (tid >> 4) & 127;
    int d  = (tid >> 11) & 127;
    int c  = tid >> 18;           // 0..15

    int spatial = d * HW_ + h * W_ + (w8 << 3);  // within-channel element offset
    int base    = c * DHW_ + spatial;

    V8 zero; 
#pragma unroll
    for (int i = 0; i < 8; i++) zero.r[i] = 0u;

    // Front-batched loads (zero outside the volume == zero padding).
    V8 v   = ldg_v8(x + base);
    V8 vhp = (h < H_ - 1) ? ldg_v8(x + base + W_)  : zero;
    V8 vhm = (h > 0)      ? ldg_v8(x + base - W_)  : zero;
    V8 vdp = (d < D_ - 1) ? ldg_v8(x + base + HW_) : zero;
    V8 vdm = (d > 0)      ? ldg_v8(x + base - HW_) : zero;

    // w-edge scalars via intra-warp shuffle. Lane-1 / lane+1 hold the adjacent
    // 8-float chunk of the same row; at row seams (w8==0 / w8==15) the result
    // is masked to zero, matching the padding.
    unsigned full = 0xffffffffu;
    uint32_t xl = __shfl_up_sync(full, v.r[7], 1);
    uint32_t xr = __shfl_down_sync(full, v.r[0], 1);
    if (w8 == 0)  xl = 0u;
    if (w8 == 15) xr = 0u;

    // w-shift taps.
    V8 k0, k1;
#pragma unroll
    for (int i = 0; i < 7; i++) k0.r[i] = v.r[i + 1];
    k0.r[7] = xr;
    k1.r[0] = xl;
#pragma unroll
    for (int i = 1; i < 8; i++) k1.r[i] = v.r[i - 1];

    // Output: flat channel ch = c*6 + k. Offset = (c*6 + k)*DHW + spatial.
    float* ob = out + (c * 6) * DHW_ + spatial;

    stg_cs_v8(ob,            k0);
    stg_cs_v8(ob + 1 * DHW_, k1);
    stg_cs_v8(ob + 2 * DHW_, vhp);
    stg_cs_v8(ob + 3 * DHW_, vhm);
    stg_cs_v8(ob + 4 * DHW_, vdp);
    stg_cs_v8(ob + 5 * DHW_, vdm);
}

extern "C" void kernel_launch(void* const* d_in, const int* in_sizes, int n_in,
                              void* d_out, int out_size)
{
    const float* x = (const float*)d_in[0];
    float* out = (float*)d_out;

    const int threads = 256;
    const int total = (C_ * DHW_) / 8;     // 4,194,304 threads
    const int blocks = total / threads;    // 16384

    stencil6_kernel<<<blocks, threads>>>(x, out);
}